// round 13
// baseline (speedup 1.0000x reference)
#include <cuda_runtime.h>
#include <cuda_bf16.h>
#include <math.h>
#include <stdint.h>

#define BB 8
#define LL 512
#define DD 512
#define HH 8
#define DH 64
#define BL 4096
#define NELEM 2097152
#define NE 5                    // 4 primary + ghost0

// ---------------- scratch (static device globals) ----------------
__device__ __nv_bfloat16 d_xn[(size_t)NE * BL * DD];
__device__ __nv_bfloat16 d_qkv[(size_t)NE * BL * 3 * DD];
__device__ __nv_bfloat16 d_attno[(size_t)NE * BL * DD];
__device__ float         d_x2[(size_t)NE * BL * DD];
__device__ __nv_bfloat16 d_ffh[(size_t)NE * BL * 4 * DD];
__device__ float         d_xout[(size_t)NE * BL * DD];
__device__ __nv_bfloat16 d_wqkvt[(size_t)NE * 3 * DD * DD];  // [N=1536][K=512]
__device__ __nv_bfloat16 d_wot[(size_t)NE * DD * DD];
__device__ __nv_bfloat16 d_w1t[(size_t)NE * 4 * DD * DD];    // [2048][512]
__device__ __nv_bfloat16 d_w2t[(size_t)NE * 4 * DD * DD];    // [512][2048]
__device__ float d_meaneo[4 * DD];
__device__ float d_stats[4];

// ---------------- helpers ----------------
__device__ __forceinline__ float warp_sum(float v) {
#pragma unroll
    for (int o = 16; o > 0; o >>= 1) v += __shfl_xor_sync(0xffffffffu, v, o);
    return v;
}
__device__ __forceinline__ float gelu_tanh(float v) {
    float c = 0.7978845608028654f * (v + 0.044715f * v * v * v);
    return 0.5f * v * (1.0f + tanhf(c));
}
__device__ __forceinline__ uint32_t packbf(float lo, float hi) {
    __nv_bfloat162 v = __floats2bfloat162_rn(lo, hi);
    return *reinterpret_cast<uint32_t*>(&v);
}
__device__ __forceinline__ void mma16(float* c, const uint32_t* a, const uint32_t* b) {
    asm volatile(
        "mma.sync.aligned.m16n8k16.row.col.f32.bf16.bf16.f32 "
        "{%0,%1,%2,%3},{%4,%5,%6,%7},{%8,%9},{%0,%1,%2,%3};\n"
        : "+f"(c[0]), "+f"(c[1]), "+f"(c[2]), "+f"(c[3])
        : "r"(a[0]), "r"(a[1]), "r"(a[2]), "r"(a[3]), "r"(b[0]), "r"(b[1]));
}
__device__ __forceinline__ void ldsm_x4(uint32_t& r0, uint32_t& r1, uint32_t& r2, uint32_t& r3,
                                        const void* p) {
    uint32_t a = (uint32_t)__cvta_generic_to_shared(p);
    asm volatile("ldmatrix.sync.aligned.m8n8.x4.shared.b16 {%0,%1,%2,%3}, [%4];\n"
                 : "=r"(r0), "=r"(r1), "=r"(r2), "=r"(r3) : "r"(a));
}
__device__ __forceinline__ void ldsm_x2_trans(uint32_t& r0, uint32_t& r1, const void* p) {
    uint32_t a = (uint32_t)__cvta_generic_to_shared(p);
    asm volatile("ldmatrix.sync.aligned.m8n8.x2.trans.shared.b16 {%0,%1}, [%2];\n"
                 : "=r"(r0), "=r"(r1) : "r"(a));
}
__device__ __forceinline__ void cpa16(void* dst, const void* src) {
    uint32_t d = (uint32_t)__cvta_generic_to_shared(dst);
    asm volatile("cp.async.cg.shared.global [%0], [%1], 16;\n" :: "r"(d), "l"(src));
}
#define CP_COMMIT() asm volatile("cp.async.commit_group;\n" ::: "memory")
#define CP_WAIT1()  asm volatile("cp.async.wait_group 1;\n" ::: "memory")
#define CP_WAIT0()  asm volatile("cp.async.wait_group 0;\n" ::: "memory")

// ---------------- fused weight transpose+bf16 for all 4 weight types, 5 experts --------------
__global__ void wtrans4_kernel(const float* p0, const float* g0, __nv_bfloat16* o0,
                               const float* p1, const float* g1, __nv_bfloat16* o1,
                               const float* p2, const float* g2, __nv_bfloat16* o2,
                               const float* p3, const float* g3, __nv_bfloat16* o3)
{
    __shared__ float s[32][33];
    int e = blockIdx.y;
    int idx = blockIdx.x;
    const float *p, *g; __nv_bfloat16* o; int K, N;
    if (idx < 768)       { p = p0; g = g0; o = o0; K = 512;  N = 1536; }
    else if (idx < 1024) { p = p1; g = g1; o = o1; K = 512;  N = 512;  idx -= 768; }
    else if (idx < 2048) { p = p2; g = g2; o = o2; K = 512;  N = 2048; idx -= 1024; }
    else                 { p = p3; g = g3; o = o3; K = 2048; N = 512;  idx -= 2048; }
    int tkx = K >> 5;
    int k0 = (idx % tkx) * 32, n0 = (idx / tkx) * 32;
    const float* in = (e < 4) ? p + (size_t)e * K * N : g;
    __nv_bfloat16* out = o + (size_t)e * K * N;
    int tx = threadIdx.x, ty = threadIdx.y;   // 32 x 8
#pragma unroll
    for (int r = 0; r < 4; r++)
        s[ty + 8 * r][tx] = in[(size_t)(k0 + ty + 8 * r) * N + n0 + tx];
    __syncthreads();
#pragma unroll
    for (int r = 0; r < 4; r++)
        out[(size_t)(n0 + ty + 8 * r) * K + k0 + tx] = __float2bfloat16_rn(s[tx][ty + 8 * r]);
}

// ---------------- LayerNorm over 5 experts; fp32 in, bf16 out ----------------
__global__ void ln5_kernel(const float* __restrict__ X, size_t sX, int xShared,
                           const float* __restrict__ sP, const float* __restrict__ sG,
                           const float* __restrict__ bP, const float* __restrict__ bG,
                           __nv_bfloat16* __restrict__ Y)
{
    __shared__ float sm[8];
    int e = blockIdx.y;
    const float* x = (xShared ? X : X + (size_t)e * sX) + (size_t)blockIdx.x * DD;
    const float* sc = (e < 4 ? sP + (size_t)e * DD : sG);
    const float* bi = (e < 4 ? bP + (size_t)e * DD : bG);
    __nv_bfloat16* y = Y + (size_t)e * NELEM + (size_t)blockIdx.x * DD;
    int t = threadIdx.x;
    float4 v = reinterpret_cast<const float4*>(x)[t];
    float s = v.x + v.y + v.z + v.w;
    float q = v.x * v.x + v.y * v.y + v.z * v.z + v.w * v.w;
    s = warp_sum(s); q = warp_sum(q);
    if ((t & 31) == 0) { sm[t >> 5] = s; sm[4 + (t >> 5)] = q; }
    __syncthreads();
    float S = sm[0] + sm[1] + sm[2] + sm[3];
    float Q = sm[4] + sm[5] + sm[6] + sm[7];
    float mean = S * (1.0f / DD);
    float var  = Q * (1.0f / DD) - mean * mean;
    float inv  = rsqrtf(var + 1e-5f);
    float4 scv = reinterpret_cast<const float4*>(sc)[t];
    float4 biv = reinterpret_cast<const float4*>(bi)[t];
    uint2 u;
    u.x = packbf((v.x - mean) * inv * scv.x + biv.x, (v.y - mean) * inv * scv.y + biv.y);
    u.y = packbf((v.z - mean) * inv * scv.z + biv.z, (v.w - mean) * inv * scv.w + biv.w);
    *reinterpret_cast<uint2*>(y + 4 * t) = u;
}

// ---------------- bf16 GEMM: 128x128 tiles, BK=32, ldmatrix fragments (R6 proven) ------------
#define AH 40
#define STGH (2 * 128 * AH)

template<int EPI, typename OT>
__global__ void __launch_bounds__(256)
gemm5bf(const __nv_bfloat16* __restrict__ Ab, size_t sA,
        const __nv_bfloat16* __restrict__ Wb, size_t sW,
        const float* __restrict__ bP, const float* __restrict__ bG, int sB,
        const float* __restrict__ Rb, size_t sR, int rShared,
        OT* __restrict__ Cb, size_t sC, int N, int K)
{
    extern __shared__ __nv_bfloat16 smh[];
    int e = blockIdx.z;
    const __nv_bfloat16* A = Ab + (size_t)e * sA;
    const __nv_bfloat16* W = Wb + (size_t)e * sW;
    const float* bias = (e < 4 ? bP + (size_t)e * sB : bG);
    const float* R = Rb ? (rShared ? Rb : Rb + (size_t)e * sR) : nullptr;
    OT* C = Cb + (size_t)e * sC;

    int tid = threadIdx.x;
    int lane = tid & 31, warp = tid >> 5;
    int g = lane >> 2, tig = lane & 3;
    int lr = lane & 7, sel = lane >> 3;
    int wm = (warp >> 1) * 32, wn = (warp & 1) * 64;
    int bm = blockIdx.y * 128, bn = blockIdx.x * 128;

    float c[2][8][4];
#pragma unroll
    for (int i = 0; i < 2; i++)
#pragma unroll
        for (int j = 0; j < 8; j++)
#pragma unroll
            for (int q = 0; q < 4; q++) c[i][j][q] = 0.f;

    int KT = K >> 5;

#pragma unroll
    for (int s = 0; s < 2; s++) {
        __nv_bfloat16* As = smh + s * STGH;
        __nv_bfloat16* Bs = As + 128 * AH;
        int k0 = s * 32;
#pragma unroll
        for (int i = 0; i < 2; i++) {
            int idx = tid + i * 256;
            int row = idx >> 2, c8 = idx & 3;
            cpa16(As + row * AH + c8 * 8, A + (size_t)(bm + row) * K + k0 + c8 * 8);
            cpa16(Bs + row * AH + c8 * 8, W + (size_t)(bn + row) * K + k0 + c8 * 8);
        }
        CP_COMMIT();
    }

    for (int it = 0; it < KT; it++) {
        CP_WAIT1();
        __syncthreads();
        const __nv_bfloat16* As = smh + (it % 3) * STGH;
        const __nv_bfloat16* Bs = As + 128 * AH;
#pragma unroll
        for (int ks = 0; ks < 2; ks++) {
            int kb = ks * 16;
            uint32_t af[2][4], bf[8][2];
#pragma unroll
            for (int mt = 0; mt < 2; mt++) {
                const __nv_bfloat16* pa =
                    As + (size_t)(wm + mt * 16 + lr + (sel & 1) * 8) * AH + kb + (sel >> 1) * 8;
                ldsm_x4(af[mt][0], af[mt][1], af[mt][2], af[mt][3], pa);
            }
#pragma unroll
            for (int nt2 = 0; nt2 < 4; nt2++) {
                const __nv_bfloat16* pb =
                    Bs + (size_t)(wn + nt2 * 16 + lr + (sel >> 1) * 8) * AH + kb + (sel & 1) * 8;
                ldsm_x4(bf[2 * nt2][0], bf[2 * nt2][1], bf[2 * nt2 + 1][0], bf[2 * nt2 + 1][1], pb);
            }
#pragma unroll
            for (int mt = 0; mt < 2; mt++)
#pragma unroll
                for (int nt = 0; nt < 8; nt++)
                    mma16(c[mt][nt], af[mt], bf[nt]);
        }
        int nx = it + 2;
        if (nx < KT) {
            __nv_bfloat16* Asw = smh + (nx % 3) * STGH;
            __nv_bfloat16* Bsw = Asw + 128 * AH;
            int k0 = nx * 32;
#pragma unroll
            for (int i = 0; i < 2; i++) {
                int idx = tid + i * 256;
                int row = idx >> 2, c8 = idx & 3;
                cpa16(Asw + row * AH + c8 * 8, A + (size_t)(bm + row) * K + k0 + c8 * 8);
                cpa16(Bsw + row * AH + c8 * 8, W + (size_t)(bn + row) * K + k0 + c8 * 8);
            }
        }
        CP_COMMIT();
    }

#pragma unroll
    for (int mt = 0; mt < 2; mt++) {
        int r0 = bm + wm + mt * 16 + g;
        int r1 = r0 + 8;
#pragma unroll
        for (int nt = 0; nt < 8; nt++) {
            int cc = bn + wn + nt * 8 + tig * 2;
            float b0 = bias[cc], b1 = bias[cc + 1];
            float v00 = c[mt][nt][0] + b0, v01 = c[mt][nt][1] + b1;
            float v10 = c[mt][nt][2] + b0, v11 = c[mt][nt][3] + b1;
            if (EPI == 1) {
                v00 = gelu_tanh(v00); v01 = gelu_tanh(v01);
                v10 = gelu_tanh(v10); v11 = gelu_tanh(v11);
            }
            if (EPI == 2) {
                v00 += R[(size_t)r0 * N + cc]; v01 += R[(size_t)r0 * N + cc + 1];
                v10 += R[(size_t)r1 * N + cc]; v11 += R[(size_t)r1 * N + cc + 1];
            }
            if (sizeof(OT) == 2) {
                *reinterpret_cast<uint32_t*>((char*)(C + (size_t)r0 * N + cc)) = packbf(v00, v01);
                *reinterpret_cast<uint32_t*>((char*)(C + (size_t)r1 * N + cc)) = packbf(v10, v11);
            } else {
                *reinterpret_cast<float2*>((char*)(C + (size_t)r0 * N + cc)) = make_float2(v00, v01);
                *reinterpret_cast<float2*>((char*)(C + (size_t)r1 * N + cc)) = make_float2(v10, v11);
            }
        }
    }
}

// ---------------- flash attention bf16: cp.async double-buffered K/V ----------------
// smem halves: Qs[128*72], then K/V buffers: {K0,V0,K1,V1} each 64*72
#define FQ 0
#define FKV (128 * 72)
#define KVSZ (64 * 72)
#define FLASH_SMEM ((FKV + 4 * KVSZ) * 2)

__global__ void __launch_bounds__(256)
flash_kernel(const __nv_bfloat16* __restrict__ qkv5, __nv_bfloat16* __restrict__ attno5)
{
    extern __shared__ __nv_bfloat16 smh[];
    __nv_bfloat16* Qs = smh + FQ;

    int e = blockIdx.z;
    const __nv_bfloat16* qkv = qkv5 + (size_t)e * BL * 3 * DD;
    __nv_bfloat16* attno = attno5 + (size_t)e * NELEM;
    int bh = blockIdx.y;
    int b = bh >> 3, h = bh & 7;
    int i0 = blockIdx.x * 128;
    int tid = threadIdx.x;
    int lane = tid & 31, warp = tid >> 5;
    int g = lane >> 2, tig = lane & 3;
    int lr = lane & 7, sel = lane >> 3;
    int wm = warp * 16;

    // prologue: stage Q + K/V tile 0 (one cp.async group)
#pragma unroll
    for (int i = 0; i < 4; i++) {
        int idx = tid + i * 256;
        int m = idx >> 3, c8 = idx & 7;
        cpa16(Qs + m * 72 + c8 * 8,
              qkv + (size_t)(b * LL + i0 + m) * (3 * DD) + h * DH + c8 * 8);
    }
    {
        __nv_bfloat16* Ks = smh + FKV;
        __nv_bfloat16* Vs = Ks + KVSZ;
#pragma unroll
        for (int i = 0; i < 2; i++) {
            int idx = tid + i * 256;
            int r = idx >> 3, c8 = idx & 7;
            cpa16(Ks + r * 72 + c8 * 8,
                  qkv + (size_t)(b * LL + r) * (3 * DD) + DD + h * DH + c8 * 8);
            cpa16(Vs + r * 72 + c8 * 8,
                  qkv + (size_t)(b * LL + r) * (3 * DD) + 2 * DD + h * DH + c8 * 8);
        }
        CP_COMMIT();
    }

    float o[8][4];
#pragma unroll
    for (int j = 0; j < 8; j++)
#pragma unroll
        for (int q = 0; q < 4; q++) o[j][q] = 0.f;
    float mrow[2] = { -1e30f, -1e30f };
    float lrow[2] = { 0.f, 0.f };

    for (int jt = 0; jt < 8; jt++) {
        __syncthreads();    // all warps done with buffer (jt+1)&1 from iteration jt-1
        if (jt + 1 < 8) {   // prefetch tile jt+1
            __nv_bfloat16* Ks = smh + FKV + ((jt + 1) & 1) * 2 * KVSZ;
            __nv_bfloat16* Vs = Ks + KVSZ;
            int j0 = (jt + 1) * 64;
#pragma unroll
            for (int i = 0; i < 2; i++) {
                int idx = tid + i * 256;
                int r = idx >> 3, c8 = idx & 7;
                cpa16(Ks + r * 72 + c8 * 8,
                      qkv + (size_t)(b * LL + j0 + r) * (3 * DD) + DD + h * DH + c8 * 8);
                cpa16(Vs + r * 72 + c8 * 8,
                      qkv + (size_t)(b * LL + j0 + r) * (3 * DD) + 2 * DD + h * DH + c8 * 8);
            }
            CP_COMMIT();
            CP_WAIT1();     // tile jt (and Q on jt=0) has landed
        } else {
            CP_WAIT0();
        }
        __syncthreads();

        const __nv_bfloat16* Ks = smh + FKV + (jt & 1) * 2 * KVSZ;
        const __nv_bfloat16* Vs = Ks + KVSZ;

        // S = Q @ K^T (16x64 per warp)
        float c[8][4];
#pragma unroll
        for (int j = 0; j < 8; j++)
#pragma unroll
            for (int q = 0; q < 4; q++) c[j][q] = 0.f;
#pragma unroll
        for (int ks = 0; ks < 4; ks++) {
            int kb = ks * 16;
            uint32_t af[4], bf[8][2];
            const __nv_bfloat16* pa =
                Qs + (size_t)(wm + lr + (sel & 1) * 8) * 72 + kb + (sel >> 1) * 8;
            ldsm_x4(af[0], af[1], af[2], af[3], pa);
#pragma unroll
            for (int nt2 = 0; nt2 < 4; nt2++) {
                const __nv_bfloat16* pb =
                    Ks + (size_t)(nt2 * 16 + lr + (sel >> 1) * 8) * 72 + kb + (sel & 1) * 8;
                ldsm_x4(bf[2 * nt2][0], bf[2 * nt2][1], bf[2 * nt2 + 1][0], bf[2 * nt2 + 1][1], pb);
            }
#pragma unroll
            for (int nt = 0; nt < 8; nt++) mma16(c[nt], af, bf[nt]);
        }
#pragma unroll
        for (int nt = 0; nt < 8; nt++)
#pragma unroll
            for (int q = 0; q < 4; q++) c[nt][q] *= 0.125f;

        // online softmax
        float mx0 = -1e30f, mx1 = -1e30f;
#pragma unroll
        for (int nt = 0; nt < 8; nt++) {
            mx0 = fmaxf(mx0, fmaxf(c[nt][0], c[nt][1]));
            mx1 = fmaxf(mx1, fmaxf(c[nt][2], c[nt][3]));
        }
        mx0 = fmaxf(mx0, __shfl_xor_sync(0xffffffffu, mx0, 1));
        mx0 = fmaxf(mx0, __shfl_xor_sync(0xffffffffu, mx0, 2));
        mx1 = fmaxf(mx1, __shfl_xor_sync(0xffffffffu, mx1, 1));
        mx1 = fmaxf(mx1, __shfl_xor_sync(0xffffffffu, mx1, 2));
        float mn0 = fmaxf(mrow[0], mx0), mn1 = fmaxf(mrow[1], mx1);
        float sc0 = __expf(mrow[0] - mn0), sc1 = __expf(mrow[1] - mn1);
        mrow[0] = mn0; mrow[1] = mn1;
        float rs0 = 0.f, rs1 = 0.f;
#pragma unroll
        for (int nt = 0; nt < 8; nt++) {
            c[nt][0] = __expf(c[nt][0] - mn0); c[nt][1] = __expf(c[nt][1] - mn0);
            c[nt][2] = __expf(c[nt][2] - mn1); c[nt][3] = __expf(c[nt][3] - mn1);
            rs0 += c[nt][0] + c[nt][1];
            rs1 += c[nt][2] + c[nt][3];
            o[nt][0] *= sc0; o[nt][1] *= sc0; o[nt][2] *= sc1; o[nt][3] *= sc1;
        }
        rs0 += __shfl_xor_sync(0xffffffffu, rs0, 1);
        rs0 += __shfl_xor_sync(0xffffffffu, rs0, 2);
        rs1 += __shfl_xor_sync(0xffffffffu, rs1, 1);
        rs1 += __shfl_xor_sync(0xffffffffu, rs1, 2);
        lrow[0] = lrow[0] * sc0 + rs0;
        lrow[1] = lrow[1] * sc1 + rs1;

        // O += P @ V ; P register-direct, V via ldmatrix.trans
        const __nv_bfloat16* vrow = Vs + (size_t)(lane & 15) * 72;
#pragma unroll
        for (int ks = 0; ks < 4; ks++) {
            uint32_t af[4];
            af[0] = packbf(c[2 * ks][0],     c[2 * ks][1]);
            af[1] = packbf(c[2 * ks][2],     c[2 * ks][3]);
            af[2] = packbf(c[2 * ks + 1][0], c[2 * ks + 1][1]);
            af[3] = packbf(c[2 * ks + 1][2], c[2 * ks + 1][3]);
            const __nv_bfloat16* vb = vrow + ks * 16 * 72;
#pragma unroll
            for (int nt = 0; nt < 8; nt++) {
                uint32_t b0, b1;
                ldsm_x2_trans(b0, b1, vb + nt * 8);
                uint32_t bfr[2] = { b0, b1 };
                mma16(o[nt], af, bfr);
            }
        }
    }

    float inv0 = __frcp_rn(lrow[0]), inv1 = __frcp_rn(lrow[1]);
    int r0 = i0 + wm + g, r1 = r0 + 8;
#pragma unroll
    for (int nt = 0; nt < 8; nt++) {
        int cc = h * DH + nt * 8 + tig * 2;
        *reinterpret_cast<uint32_t*>(attno + (size_t)(b * LL + r0) * DD + cc) =
            packbf(o[nt][0] * inv0, o[nt][1] * inv0);
        *reinterpret_cast<uint32_t*>(attno + (size_t)(b * LL + r1) * DD + cc) =
            packbf(o[nt][2] * inv1, o[nt][3] * inv1);
    }
}

// ---------------- fused stats: per-expert column sums + uvar partials (one pass) -------------
__global__ void stats_kernel(const float* __restrict__ x, const float* __restrict__ xout5,
                             float* __restrict__ meaneo, float* __restrict__ stats)
{
    __shared__ float sm[32];
    const float* a0 = xout5;
    const float* a1 = xout5 + (size_t)NELEM;
    const float* a2 = xout5 + (size_t)2 * NELEM;
    const float* a3 = xout5 + (size_t)3 * NELEM;
    int t = threadIdx.x;                 // 512 (one per column)
    int r0 = blockIdx.x * 128;
    float m0 = 0.f, m1 = 0.f, m2 = 0.f, m3 = 0.f, s1 = 0.f, s2 = 0.f;
    for (int r = r0; r < r0 + 128; r++) {
        size_t idx = (size_t)r * DD + t;
        float v0 = a0[idx], v1 = a1[idx], v2 = a2[idx], v3 = a3[idx];
        m0 += v0; m1 += v1; m2 += v2; m3 += v3;
        float d = x[idx] - 0.25f * (v0 + v1 + v2 + v3);
        s1 += d; s2 += d * d;
    }
    atomicAdd(&meaneo[t], m0);
    atomicAdd(&meaneo[DD + t], m1);
    atomicAdd(&meaneo[2 * DD + t], m2);
    atomicAdd(&meaneo[3 * DD + t], m3);
    s1 = warp_sum(s1); s2 = warp_sum(s2);
    int w = t >> 5;                      // 16 warps
    if ((t & 31) == 0) { sm[w] = s1; sm[16 + w] = s2; }
    __syncthreads();
    if (t == 0) {
        float a = 0.f, b = 0.f;
        for (int i = 0; i < 16; i++) { a += sm[i]; b += sm[16 + i]; }
        atomicAdd(&stats[0], a);
        atomicAdd(&stats[1], b);
    }
}

// ---------------- gram / ortho / uvar / rate ----------------
__global__ void finalize_kernel(const float* __restrict__ meaneo, float* __restrict__ stats)
{
    __shared__ float sd[16];
    int t = threadIdx.x;
    if (t < 16) sd[t] = 0.f;
    __syncthreads();
    float l[4][4] = {};
    for (int c = t; c < DD; c += 256) {
        float v[4];
#pragma unroll
        for (int i = 0; i < 4; i++) v[i] = meaneo[i * DD + c];
#pragma unroll
        for (int i = 0; i < 4; i++)
#pragma unroll
            for (int j = i; j < 4; j++) l[i][j] += v[i] * v[j];
    }
#pragma unroll
    for (int i = 0; i < 4; i++)
#pragma unroll
        for (int j = i; j < 4; j++) atomicAdd(&sd[i * 4 + j], l[i][j]);
    __syncthreads();
    if (t == 0) {
        float nrm[4];
        for (int i = 0; i < 4; i++) nrm[i] = sqrtf(sd[i * 4 + i]);
        float off = 0.f;
        for (int i = 0; i < 4; i++)
            for (int j = 0; j < 4; j++) {
                float dot = (i <= j) ? sd[i * 4 + j] : sd[j * 4 + i];
                float gg = dot / (nrm[i] * nrm[j]);
                float dlt = gg - (i == j ? 1.0f : 0.0f);
                off += dlt * dlt;
            }
        float ortho = 1.0f - off / 16.0f;
        float S1 = stats[0], S2 = stats[1];
        const float N = (float)NELEM;
        float uvar = (S2 - S1 * S1 / N) / (N - 1.0f);
        float sat = ortho * uvar;
        stats[2] = (sat > 0.01f) ? 0.01f : 0.0f;
    }
}

// ---------------- combine: (sum_prim + rate * ghost0) / 6 ----------------
__global__ void combine_kernel(const float* __restrict__ xout5,
                               const float* __restrict__ stats, float* __restrict__ out)
{
    float rate = stats[2];
    const float inv6 = 1.0f / 6.0f;
    const float4* a0 = reinterpret_cast<const float4*>(xout5);
    const float4* a1 = reinterpret_cast<const float4*>(xout5 + (size_t)NELEM);
    const float4* a2 = reinterpret_cast<const float4*>(xout5 + (size_t)2 * NELEM);
    const float4* a3 = reinterpret_cast<const float4*>(xout5 + (size_t)3 * NELEM);
    const float4* gh = reinterpret_cast<const float4*>(xout5 + (size_t)4 * NELEM);
    size_t stride = (size_t)gridDim.x * blockDim.x;
    for (size_t i = (size_t)blockIdx.x * blockDim.x + threadIdx.x; i < NELEM / 4; i += stride) {
        float4 s0 = a0[i], s1 = a1[i], s2 = a2[i], s3 = a3[i], g = gh[i];
        float4 o;
        o.x = (s0.x + s1.x + s2.x + s3.x + rate * g.x) * inv6;
        o.y = (s0.y + s1.y + s2.y + s3.y + rate * g.y) * inv6;
        o.z = (s0.z + s1.z + s2.z + s3.z + rate * g.z) * inv6;
        o.w = (s0.w + s1.w + s2.w + s3.w + rate * g.w) * inv6;
        reinterpret_cast<float4*>(out)[i] = o;
    }
}

// ---------------- orchestration ----------------
extern "C" void kernel_launch(void* const* d_in, const int* in_sizes, int n_in,
                              void* d_out, int out_size)
{
    const float* x = (const float*)d_in[0];
    const float* p[12];
    const float* g[12];
    for (int i = 0; i < 12; i++) p[i] = (const float*)d_in[2 + i];
    for (int i = 0; i < 12; i++) g[i] = (const float*)d_in[14 + i];

    __nv_bfloat16 *xn, *qkv, *attno, *ffh, *wqkvt, *wot, *w1t, *w2t;
    float *x2, *xout, *meaneo, *stats;
    cudaGetSymbolAddress((void**)&xn, d_xn);
    cudaGetSymbolAddress((void**)&qkv, d_qkv);
    cudaGetSymbolAddress((void**)&attno, d_attno);
    cudaGetSymbolAddress((void**)&x2, d_x2);
    cudaGetSymbolAddress((void**)&ffh, d_ffh);
    cudaGetSymbolAddress((void**)&xout, d_xout);
    cudaGetSymbolAddress((void**)&meaneo, d_meaneo);
    cudaGetSymbolAddress((void**)&stats, d_stats);
    cudaGetSymbolAddress((void**)&wqkvt, d_wqkvt);
    cudaGetSymbolAddress((void**)&wot, d_wot);
    cudaGetSymbolAddress((void**)&w1t, d_w1t);
    cudaGetSymbolAddress((void**)&w2t, d_w2t);

    const int GEMM_SMEM = STGH * 3 * 2;
    cudaFuncSetAttribute(gemm5bf<0, __nv_bfloat16>, cudaFuncAttributeMaxDynamicSharedMemorySize, GEMM_SMEM);
    cudaFuncSetAttribute(gemm5bf<1, __nv_bfloat16>, cudaFuncAttributeMaxDynamicSharedMemorySize, GEMM_SMEM);
    cudaFuncSetAttribute(gemm5bf<2, float>,         cudaFuncAttributeMaxDynamicSharedMemorySize, GEMM_SMEM);
    cudaFuncSetAttribute(flash_kernel,              cudaFuncAttributeMaxDynamicSharedMemorySize, FLASH_SMEM);

    cudaMemsetAsync(meaneo, 0, 4 * DD * sizeof(float));
    cudaMemsetAsync(stats, 0, 4 * sizeof(float));

    // fused weight transpose+bf16
    wtrans4_kernel<<<dim3(3072, NE), dim3(32, 8)>>>(
        p[2], g[2], wqkvt, p[4], g[4], wot, p[8], g[8], w1t, p[10], g[10], w2t);

    // LN1 (x shared)
    ln5_kernel<<<dim3(BL, NE), 128>>>(x, 0, 1, p[0], g[0], p[1], g[1], xn);
    // QKV
    gemm5bf<0, __nv_bfloat16><<<dim3(12, 32, NE), 256, GEMM_SMEM>>>(
        xn, (size_t)NELEM, wqkvt, (size_t)3 * DD * DD,
        p[3], g[3], 3 * DD, nullptr, 0, 0, qkv, (size_t)BL * 3 * DD, 3 * DD, DD);
    // flash attention
    flash_kernel<<<dim3(4, 64, NE), 256, FLASH_SMEM>>>(qkv, attno);
    // O projection + residual(x)
    gemm5bf<2, float><<<dim3(4, 32, NE), 256, GEMM_SMEM>>>(
        attno, (size_t)NELEM, wot, (size_t)DD * DD,
        p[5], g[5], DD, x, 0, 1, x2, (size_t)NELEM, DD, DD);
    // LN2
    ln5_kernel<<<dim3(BL, NE), 128>>>(x2, (size_t)NELEM, 0, p[6], g[6], p[7], g[7], xn);
    // FFN1 + gelu
    gemm5bf<1, __nv_bfloat16><<<dim3(16, 32, NE), 256, GEMM_SMEM>>>(
        xn, (size_t)NELEM, w1t, (size_t)4 * DD * DD,
        p[9], g[9], 4 * DD, nullptr, 0, 0, ffh, (size_t)BL * 4 * DD, 4 * DD, DD);
    // FFN2 + residual(x2)
    gemm5bf<2, float><<<dim3(4, 32, NE), 256, GEMM_SMEM>>>(
        ffh, (size_t)BL * 4 * DD, w2t, (size_t)4 * DD * DD,
        p[11], g[11], DD, x2, (size_t)NELEM, 0, xout, (size_t)NELEM, DD, 4 * DD);

    // fused stats + finalize + combine
    stats_kernel<<<32, 512>>>(x, xout, meaneo, stats);
    finalize_kernel<<<1, 256>>>(meaneo, stats);
    combine_kernel<<<1024, 256>>>(xout, stats, (float*)d_out);
}

// round 14
// speedup vs baseline: 1.0033x; 1.0033x over previous
#include <cuda_runtime.h>
#include <cuda_bf16.h>
#include <math.h>
#include <stdint.h>

#define BB 8
#define LL 512
#define DD 512
#define HH 8
#define DH 64
#define BL 4096
#define NELEM 2097152
#define NE 5                    // 4 primary + ghost0

// ---------------- scratch (static device globals) ----------------
__device__ __nv_bfloat16 d_xn[(size_t)NE * BL * DD];
__device__ __nv_bfloat16 d_qkv[(size_t)NE * BL * 3 * DD];
__device__ __nv_bfloat16 d_attno[(size_t)NE * BL * DD];
__device__ float         d_x2[(size_t)NE * BL * DD];
__device__ __nv_bfloat16 d_ffh[(size_t)NE * BL * 4 * DD];
__device__ float         d_xout[(size_t)NE * BL * DD];
__device__ __nv_bfloat16 d_wqkvt[(size_t)NE * 3 * DD * DD];  // [N=1536][K=512]
__device__ __nv_bfloat16 d_wot[(size_t)NE * DD * DD];
__device__ __nv_bfloat16 d_w1t[(size_t)NE * 4 * DD * DD];    // [2048][512]
__device__ __nv_bfloat16 d_w2t[(size_t)NE * 4 * DD * DD];    // [512][2048]
__device__ float d_meaneo[4 * DD];
__device__ float d_stats[4];

// ---------------- helpers ----------------
__device__ __forceinline__ float warp_sum(float v) {
#pragma unroll
    for (int o = 16; o > 0; o >>= 1) v += __shfl_xor_sync(0xffffffffu, v, o);
    return v;
}
__device__ __forceinline__ float gelu_tanh(float v) {
    float c = 0.7978845608028654f * (v + 0.044715f * v * v * v);
    return 0.5f * v * (1.0f + tanhf(c));
}
__device__ __forceinline__ uint32_t packbf(float lo, float hi) {
    __nv_bfloat162 v = __floats2bfloat162_rn(lo, hi);
    return *reinterpret_cast<uint32_t*>(&v);
}
__device__ __forceinline__ void mma16(float* c, const uint32_t* a, const uint32_t* b) {
    asm volatile(
        "mma.sync.aligned.m16n8k16.row.col.f32.bf16.bf16.f32 "
        "{%0,%1,%2,%3},{%4,%5,%6,%7},{%8,%9},{%0,%1,%2,%3};\n"
        : "+f"(c[0]), "+f"(c[1]), "+f"(c[2]), "+f"(c[3])
        : "r"(a[0]), "r"(a[1]), "r"(a[2]), "r"(a[3]), "r"(b[0]), "r"(b[1]));
}
__device__ __forceinline__ void ldsm_x4(uint32_t& r0, uint32_t& r1, uint32_t& r2, uint32_t& r3,
                                        const void* p) {
    uint32_t a = (uint32_t)__cvta_generic_to_shared(p);
    asm volatile("ldmatrix.sync.aligned.m8n8.x4.shared.b16 {%0,%1,%2,%3}, [%4];\n"
                 : "=r"(r0), "=r"(r1), "=r"(r2), "=r"(r3) : "r"(a));
}
__device__ __forceinline__ void ldsm_x2_trans(uint32_t& r0, uint32_t& r1, const void* p) {
    uint32_t a = (uint32_t)__cvta_generic_to_shared(p);
    asm volatile("ldmatrix.sync.aligned.m8n8.x2.trans.shared.b16 {%0,%1}, [%2];\n"
                 : "=r"(r0), "=r"(r1) : "r"(a));
}
__device__ __forceinline__ void cpa16(void* dst, const void* src) {
    uint32_t d = (uint32_t)__cvta_generic_to_shared(dst);
    asm volatile("cp.async.cg.shared.global [%0], [%1], 16;\n" :: "r"(d), "l"(src));
}
#define CP_COMMIT() asm volatile("cp.async.commit_group;\n" ::: "memory")
#define CP_WAIT1()  asm volatile("cp.async.wait_group 1;\n" ::: "memory")
#define CP_WAIT0()  asm volatile("cp.async.wait_group 0;\n" ::: "memory")

// ---------------- fused weight transpose+bf16 for all 4 weight types, 5 experts --------------
__global__ void wtrans4_kernel(const float* p0, const float* g0, __nv_bfloat16* o0,
                               const float* p1, const float* g1, __nv_bfloat16* o1,
                               const float* p2, const float* g2, __nv_bfloat16* o2,
                               const float* p3, const float* g3, __nv_bfloat16* o3)
{
    __shared__ float s[32][33];
    int e = blockIdx.y;
    int idx = blockIdx.x;
    const float *p, *g; __nv_bfloat16* o; int K, N;
    if (idx < 768)       { p = p0; g = g0; o = o0; K = 512;  N = 1536; }
    else if (idx < 1024) { p = p1; g = g1; o = o1; K = 512;  N = 512;  idx -= 768; }
    else if (idx < 2048) { p = p2; g = g2; o = o2; K = 512;  N = 2048; idx -= 1024; }
    else                 { p = p3; g = g3; o = o3; K = 2048; N = 512;  idx -= 2048; }
    int tkx = K >> 5;
    int k0 = (idx % tkx) * 32, n0 = (idx / tkx) * 32;
    const float* in = (e < 4) ? p + (size_t)e * K * N : g;
    __nv_bfloat16* out = o + (size_t)e * K * N;
    int tx = threadIdx.x, ty = threadIdx.y;   // 32 x 8
#pragma unroll
    for (int r = 0; r < 4; r++)
        s[ty + 8 * r][tx] = in[(size_t)(k0 + ty + 8 * r) * N + n0 + tx];
    __syncthreads();
#pragma unroll
    for (int r = 0; r < 4; r++)
        out[(size_t)(n0 + ty + 8 * r) * K + k0 + tx] = __float2bfloat16_rn(s[tx][ty + 8 * r]);
}

// ---------------- LayerNorm over 5 experts; fp32 in, bf16 out ----------------
__global__ void ln5_kernel(const float* __restrict__ X, size_t sX, int xShared,
                           const float* __restrict__ sP, const float* __restrict__ sG,
                           const float* __restrict__ bP, const float* __restrict__ bG,
                           __nv_bfloat16* __restrict__ Y)
{
    __shared__ float sm[8];
    int e = blockIdx.y;
    const float* x = (xShared ? X : X + (size_t)e * sX) + (size_t)blockIdx.x * DD;
    const float* sc = (e < 4 ? sP + (size_t)e * DD : sG);
    const float* bi = (e < 4 ? bP + (size_t)e * DD : bG);
    __nv_bfloat16* y = Y + (size_t)e * NELEM + (size_t)blockIdx.x * DD;
    int t = threadIdx.x;
    float4 v = reinterpret_cast<const float4*>(x)[t];
    float s = v.x + v.y + v.z + v.w;
    float q = v.x * v.x + v.y * v.y + v.z * v.z + v.w * v.w;
    s = warp_sum(s); q = warp_sum(q);
    if ((t & 31) == 0) { sm[t >> 5] = s; sm[4 + (t >> 5)] = q; }
    __syncthreads();
    float S = sm[0] + sm[1] + sm[2] + sm[3];
    float Q = sm[4] + sm[5] + sm[6] + sm[7];
    float mean = S * (1.0f / DD);
    float var  = Q * (1.0f / DD) - mean * mean;
    float inv  = rsqrtf(var + 1e-5f);
    float4 scv = reinterpret_cast<const float4*>(sc)[t];
    float4 biv = reinterpret_cast<const float4*>(bi)[t];
    uint2 u;
    u.x = packbf((v.x - mean) * inv * scv.x + biv.x, (v.y - mean) * inv * scv.y + biv.y);
    u.y = packbf((v.z - mean) * inv * scv.z + biv.z, (v.w - mean) * inv * scv.w + biv.w);
    *reinterpret_cast<uint2*>(y + 4 * t) = u;
}

// ---------------- bf16 GEMM: 128x128 tiles, BK=32, ldmatrix fragments (R6 proven) ------------
#define AH 40
#define STGH (2 * 128 * AH)

template<int EPI, typename OT>
__global__ void __launch_bounds__(256)
gemm5bf(const __nv_bfloat16* __restrict__ Ab, size_t sA,
        const __nv_bfloat16* __restrict__ Wb, size_t sW,
        const float* __restrict__ bP, const float* __restrict__ bG, int sB,
        const float* __restrict__ Rb, size_t sR, int rShared,
        OT* __restrict__ Cb, size_t sC, int N, int K)
{
    extern __shared__ __nv_bfloat16 smh[];
    int e = blockIdx.z;
    const __nv_bfloat16* A = Ab + (size_t)e * sA;
    const __nv_bfloat16* W = Wb + (size_t)e * sW;
    const float* bias = (e < 4 ? bP + (size_t)e * sB : bG);
    const float* R = Rb ? (rShared ? Rb : Rb + (size_t)e * sR) : nullptr;
    OT* C = Cb + (size_t)e * sC;

    int tid = threadIdx.x;
    int lane = tid & 31, warp = tid >> 5;
    int g = lane >> 2, tig = lane & 3;
    int lr = lane & 7, sel = lane >> 3;
    int wm = (warp >> 1) * 32, wn = (warp & 1) * 64;
    int bm = blockIdx.y * 128, bn = blockIdx.x * 128;

    float c[2][8][4];
#pragma unroll
    for (int i = 0; i < 2; i++)
#pragma unroll
        for (int j = 0; j < 8; j++)
#pragma unroll
            for (int q = 0; q < 4; q++) c[i][j][q] = 0.f;

    int KT = K >> 5;

#pragma unroll
    for (int s = 0; s < 2; s++) {
        __nv_bfloat16* As = smh + s * STGH;
        __nv_bfloat16* Bs = As + 128 * AH;
        int k0 = s * 32;
#pragma unroll
        for (int i = 0; i < 2; i++) {
            int idx = tid + i * 256;
            int row = idx >> 2, c8 = idx & 3;
            cpa16(As + row * AH + c8 * 8, A + (size_t)(bm + row) * K + k0 + c8 * 8);
            cpa16(Bs + row * AH + c8 * 8, W + (size_t)(bn + row) * K + k0 + c8 * 8);
        }
        CP_COMMIT();
    }

    for (int it = 0; it < KT; it++) {
        CP_WAIT1();
        __syncthreads();
        const __nv_bfloat16* As = smh + (it % 3) * STGH;
        const __nv_bfloat16* Bs = As + 128 * AH;
#pragma unroll
        for (int ks = 0; ks < 2; ks++) {
            int kb = ks * 16;
            uint32_t af[2][4], bf[8][2];
#pragma unroll
            for (int mt = 0; mt < 2; mt++) {
                const __nv_bfloat16* pa =
                    As + (size_t)(wm + mt * 16 + lr + (sel & 1) * 8) * AH + kb + (sel >> 1) * 8;
                ldsm_x4(af[mt][0], af[mt][1], af[mt][2], af[mt][3], pa);
            }
#pragma unroll
            for (int nt2 = 0; nt2 < 4; nt2++) {
                const __nv_bfloat16* pb =
                    Bs + (size_t)(wn + nt2 * 16 + lr + (sel >> 1) * 8) * AH + kb + (sel & 1) * 8;
                ldsm_x4(bf[2 * nt2][0], bf[2 * nt2][1], bf[2 * nt2 + 1][0], bf[2 * nt2 + 1][1], pb);
            }
#pragma unroll
            for (int mt = 0; mt < 2; mt++)
#pragma unroll
                for (int nt = 0; nt < 8; nt++)
                    mma16(c[mt][nt], af[mt], bf[nt]);
        }
        int nx = it + 2;
        if (nx < KT) {
            __nv_bfloat16* Asw = smh + (nx % 3) * STGH;
            __nv_bfloat16* Bsw = Asw + 128 * AH;
            int k0 = nx * 32;
#pragma unroll
            for (int i = 0; i < 2; i++) {
                int idx = tid + i * 256;
                int row = idx >> 2, c8 = idx & 3;
                cpa16(Asw + row * AH + c8 * 8, A + (size_t)(bm + row) * K + k0 + c8 * 8);
                cpa16(Bsw + row * AH + c8 * 8, W + (size_t)(bn + row) * K + k0 + c8 * 8);
            }
        }
        CP_COMMIT();
    }

#pragma unroll
    for (int mt = 0; mt < 2; mt++) {
        int r0 = bm + wm + mt * 16 + g;
        int r1 = r0 + 8;
#pragma unroll
        for (int nt = 0; nt < 8; nt++) {
            int cc = bn + wn + nt * 8 + tig * 2;
            float b0 = bias[cc], b1 = bias[cc + 1];
            float v00 = c[mt][nt][0] + b0, v01 = c[mt][nt][1] + b1;
            float v10 = c[mt][nt][2] + b0, v11 = c[mt][nt][3] + b1;
            if (EPI == 1) {
                v00 = gelu_tanh(v00); v01 = gelu_tanh(v01);
                v10 = gelu_tanh(v10); v11 = gelu_tanh(v11);
            }
            if (EPI == 2) {
                v00 += R[(size_t)r0 * N + cc]; v01 += R[(size_t)r0 * N + cc + 1];
                v10 += R[(size_t)r1 * N + cc]; v11 += R[(size_t)r1 * N + cc + 1];
            }
            if (sizeof(OT) == 2) {
                *reinterpret_cast<uint32_t*>((char*)(C + (size_t)r0 * N + cc)) = packbf(v00, v01);
                *reinterpret_cast<uint32_t*>((char*)(C + (size_t)r1 * N + cc)) = packbf(v10, v11);
            } else {
                *reinterpret_cast<float2*>((char*)(C + (size_t)r0 * N + cc)) = make_float2(v00, v01);
                *reinterpret_cast<float2*>((char*)(C + (size_t)r1 * N + cc)) = make_float2(v10, v11);
            }
        }
    }
}

// ---------------- flash attention bf16: cp.async double-buffered K/V ----------------
// smem halves: Qs[128*72], then K/V buffers: {K0,V0,K1,V1} each 64*72
#define FQ 0
#define FKV (128 * 72)
#define KVSZ (64 * 72)
#define FLASH_SMEM ((FKV + 4 * KVSZ) * 2)

__global__ void __launch_bounds__(256)
flash_kernel(const __nv_bfloat16* __restrict__ qkv5, __nv_bfloat16* __restrict__ attno5)
{
    extern __shared__ __nv_bfloat16 smh[];
    __nv_bfloat16* Qs = smh + FQ;

    int e = blockIdx.z;
    const __nv_bfloat16* qkv = qkv5 + (size_t)e * BL * 3 * DD;
    __nv_bfloat16* attno = attno5 + (size_t)e * NELEM;
    int bh = blockIdx.y;
    int b = bh >> 3, h = bh & 7;
    int i0 = blockIdx.x * 128;
    int tid = threadIdx.x;
    int lane = tid & 31, warp = tid >> 5;
    int g = lane >> 2, tig = lane & 3;
    int lr = lane & 7, sel = lane >> 3;
    int wm = warp * 16;

    // prologue: stage Q + K/V tile 0 (one cp.async group)
#pragma unroll
    for (int i = 0; i < 4; i++) {
        int idx = tid + i * 256;
        int m = idx >> 3, c8 = idx & 7;
        cpa16(Qs + m * 72 + c8 * 8,
              qkv + (size_t)(b * LL + i0 + m) * (3 * DD) + h * DH + c8 * 8);
    }
    {
        __nv_bfloat16* Ks = smh + FKV;
        __nv_bfloat16* Vs = Ks + KVSZ;
#pragma unroll
        for (int i = 0; i < 2; i++) {
            int idx = tid + i * 256;
            int r = idx >> 3, c8 = idx & 7;
            cpa16(Ks + r * 72 + c8 * 8,
                  qkv + (size_t)(b * LL + r) * (3 * DD) + DD + h * DH + c8 * 8);
            cpa16(Vs + r * 72 + c8 * 8,
                  qkv + (size_t)(b * LL + r) * (3 * DD) + 2 * DD + h * DH + c8 * 8);
        }
        CP_COMMIT();
    }

    float o[8][4];
#pragma unroll
    for (int j = 0; j < 8; j++)
#pragma unroll
        for (int q = 0; q < 4; q++) o[j][q] = 0.f;
    float mrow[2] = { -1e30f, -1e30f };
    float lrow[2] = { 0.f, 0.f };

    for (int jt = 0; jt < 8; jt++) {
        __syncthreads();    // all warps done with buffer (jt+1)&1 from iteration jt-1
        if (jt + 1 < 8) {   // prefetch tile jt+1
            __nv_bfloat16* Ks = smh + FKV + ((jt + 1) & 1) * 2 * KVSZ;
            __nv_bfloat16* Vs = Ks + KVSZ;
            int j0 = (jt + 1) * 64;
#pragma unroll
            for (int i = 0; i < 2; i++) {
                int idx = tid + i * 256;
                int r = idx >> 3, c8 = idx & 7;
                cpa16(Ks + r * 72 + c8 * 8,
                      qkv + (size_t)(b * LL + j0 + r) * (3 * DD) + DD + h * DH + c8 * 8);
                cpa16(Vs + r * 72 + c8 * 8,
                      qkv + (size_t)(b * LL + j0 + r) * (3 * DD) + 2 * DD + h * DH + c8 * 8);
            }
            CP_COMMIT();
            CP_WAIT1();     // tile jt (and Q on jt=0) has landed
        } else {
            CP_WAIT0();
        }
        __syncthreads();

        const __nv_bfloat16* Ks = smh + FKV + (jt & 1) * 2 * KVSZ;
        const __nv_bfloat16* Vs = Ks + KVSZ;

        // S = Q @ K^T (16x64 per warp)
        float c[8][4];
#pragma unroll
        for (int j = 0; j < 8; j++)
#pragma unroll
            for (int q = 0; q < 4; q++) c[j][q] = 0.f;
#pragma unroll
        for (int ks = 0; ks < 4; ks++) {
            int kb = ks * 16;
            uint32_t af[4], bf[8][2];
            const __nv_bfloat16* pa =
                Qs + (size_t)(wm + lr + (sel & 1) * 8) * 72 + kb + (sel >> 1) * 8;
            ldsm_x4(af[0], af[1], af[2], af[3], pa);
#pragma unroll
            for (int nt2 = 0; nt2 < 4; nt2++) {
                const __nv_bfloat16* pb =
                    Ks + (size_t)(nt2 * 16 + lr + (sel >> 1) * 8) * 72 + kb + (sel & 1) * 8;
                ldsm_x4(bf[2 * nt2][0], bf[2 * nt2][1], bf[2 * nt2 + 1][0], bf[2 * nt2 + 1][1], pb);
            }
#pragma unroll
            for (int nt = 0; nt < 8; nt++) mma16(c[nt], af, bf[nt]);
        }
#pragma unroll
        for (int nt = 0; nt < 8; nt++)
#pragma unroll
            for (int q = 0; q < 4; q++) c[nt][q] *= 0.125f;

        // online softmax
        float mx0 = -1e30f, mx1 = -1e30f;
#pragma unroll
        for (int nt = 0; nt < 8; nt++) {
            mx0 = fmaxf(mx0, fmaxf(c[nt][0], c[nt][1]));
            mx1 = fmaxf(mx1, fmaxf(c[nt][2], c[nt][3]));
        }
        mx0 = fmaxf(mx0, __shfl_xor_sync(0xffffffffu, mx0, 1));
        mx0 = fmaxf(mx0, __shfl_xor_sync(0xffffffffu, mx0, 2));
        mx1 = fmaxf(mx1, __shfl_xor_sync(0xffffffffu, mx1, 1));
        mx1 = fmaxf(mx1, __shfl_xor_sync(0xffffffffu, mx1, 2));
        float mn0 = fmaxf(mrow[0], mx0), mn1 = fmaxf(mrow[1], mx1);
        float sc0 = __expf(mrow[0] - mn0), sc1 = __expf(mrow[1] - mn1);
        mrow[0] = mn0; mrow[1] = mn1;
        float rs0 = 0.f, rs1 = 0.f;
#pragma unroll
        for (int nt = 0; nt < 8; nt++) {
            c[nt][0] = __expf(c[nt][0] - mn0); c[nt][1] = __expf(c[nt][1] - mn0);
            c[nt][2] = __expf(c[nt][2] - mn1); c[nt][3] = __expf(c[nt][3] - mn1);
            rs0 += c[nt][0] + c[nt][1];
            rs1 += c[nt][2] + c[nt][3];
            o[nt][0] *= sc0; o[nt][1] *= sc0; o[nt][2] *= sc1; o[nt][3] *= sc1;
        }
        rs0 += __shfl_xor_sync(0xffffffffu, rs0, 1);
        rs0 += __shfl_xor_sync(0xffffffffu, rs0, 2);
        rs1 += __shfl_xor_sync(0xffffffffu, rs1, 1);
        rs1 += __shfl_xor_sync(0xffffffffu, rs1, 2);
        lrow[0] = lrow[0] * sc0 + rs0;
        lrow[1] = lrow[1] * sc1 + rs1;

        // O += P @ V ; P register-direct, V via ldmatrix.trans
        const __nv_bfloat16* vrow = Vs + (size_t)(lane & 15) * 72;
#pragma unroll
        for (int ks = 0; ks < 4; ks++) {
            uint32_t af[4];
            af[0] = packbf(c[2 * ks][0],     c[2 * ks][1]);
            af[1] = packbf(c[2 * ks][2],     c[2 * ks][3]);
            af[2] = packbf(c[2 * ks + 1][0], c[2 * ks + 1][1]);
            af[3] = packbf(c[2 * ks + 1][2], c[2 * ks + 1][3]);
            const __nv_bfloat16* vb = vrow + ks * 16 * 72;
#pragma unroll
            for (int nt = 0; nt < 8; nt++) {
                uint32_t b0, b1;
                ldsm_x2_trans(b0, b1, vb + nt * 8);
                uint32_t bfr[2] = { b0, b1 };
                mma16(o[nt], af, bfr);
            }
        }
    }

    float inv0 = __frcp_rn(lrow[0]), inv1 = __frcp_rn(lrow[1]);
    int r0 = i0 + wm + g, r1 = r0 + 8;
#pragma unroll
    for (int nt = 0; nt < 8; nt++) {
        int cc = h * DH + nt * 8 + tig * 2;
        *reinterpret_cast<uint32_t*>(attno + (size_t)(b * LL + r0) * DD + cc) =
            packbf(o[nt][0] * inv0, o[nt][1] * inv0);
        *reinterpret_cast<uint32_t*>(attno + (size_t)(b * LL + r1) * DD + cc) =
            packbf(o[nt][2] * inv1, o[nt][3] * inv1);
    }
}

// ---------------- fused stats: per-expert column sums + uvar partials (one pass) -------------
__global__ void stats_kernel(const float* __restrict__ x, const float* __restrict__ xout5,
                             float* __restrict__ meaneo, float* __restrict__ stats)
{
    __shared__ float sm[32];
    const float* a0 = xout5;
    const float* a1 = xout5 + (size_t)NELEM;
    const float* a2 = xout5 + (size_t)2 * NELEM;
    const float* a3 = xout5 + (size_t)3 * NELEM;
    int t = threadIdx.x;                 // 512 (one per column)
    int r0 = blockIdx.x * 128;
    float m0 = 0.f, m1 = 0.f, m2 = 0.f, m3 = 0.f, s1 = 0.f, s2 = 0.f;
    for (int r = r0; r < r0 + 128; r++) {
        size_t idx = (size_t)r * DD + t;
        float v0 = a0[idx], v1 = a1[idx], v2 = a2[idx], v3 = a3[idx];
        m0 += v0; m1 += v1; m2 += v2; m3 += v3;
        float d = x[idx] - 0.25f * (v0 + v1 + v2 + v3);
        s1 += d; s2 += d * d;
    }
    atomicAdd(&meaneo[t], m0);
    atomicAdd(&meaneo[DD + t], m1);
    atomicAdd(&meaneo[2 * DD + t], m2);
    atomicAdd(&meaneo[3 * DD + t], m3);
    s1 = warp_sum(s1); s2 = warp_sum(s2);
    int w = t >> 5;                      // 16 warps
    if ((t & 31) == 0) { sm[w] = s1; sm[16 + w] = s2; }
    __syncthreads();
    if (t == 0) {
        float a = 0.f, b = 0.f;
        for (int i = 0; i < 16; i++) { a += sm[i]; b += sm[16 + i]; }
        atomicAdd(&stats[0], a);
        atomicAdd(&stats[1], b);
    }
}

// ---------------- gram / ortho / uvar / rate ----------------
__global__ void finalize_kernel(const float* __restrict__ meaneo, float* __restrict__ stats)
{
    __shared__ float sd[16];
    int t = threadIdx.x;
    if (t < 16) sd[t] = 0.f;
    __syncthreads();
    float l[4][4] = {};
    for (int c = t; c < DD; c += 256) {
        float v[4];
#pragma unroll
        for (int i = 0; i < 4; i++) v[i] = meaneo[i * DD + c];
#pragma unroll
        for (int i = 0; i < 4; i++)
#pragma unroll
            for (int j = i; j < 4; j++) l[i][j] += v[i] * v[j];
    }
#pragma unroll
    for (int i = 0; i < 4; i++)
#pragma unroll
        for (int j = i; j < 4; j++) atomicAdd(&sd[i * 4 + j], l[i][j]);
    __syncthreads();
    if (t == 0) {
        float nrm[4];
        for (int i = 0; i < 4; i++) nrm[i] = sqrtf(sd[i * 4 + i]);
        float off = 0.f;
        for (int i = 0; i < 4; i++)
            for (int j = 0; j < 4; j++) {
                float dot = (i <= j) ? sd[i * 4 + j] : sd[j * 4 + i];
                float gg = dot / (nrm[i] * nrm[j]);
                float dlt = gg - (i == j ? 1.0f : 0.0f);
                off += dlt * dlt;
            }
        float ortho = 1.0f - off / 16.0f;
        float S1 = stats[0], S2 = stats[1];
        const float N = (float)NELEM;
        float uvar = (S2 - S1 * S1 / N) / (N - 1.0f);
        float sat = ortho * uvar;
        stats[2] = (sat > 0.01f) ? 0.01f : 0.0f;
    }
}

// ---------------- combine: (sum_prim + rate * ghost0) / 6 ----------------
__global__ void combine_kernel(const float* __restrict__ xout5,
                               const float* __restrict__ stats, float* __restrict__ out)
{
    float rate = stats[2];
    const float inv6 = 1.0f / 6.0f;
    const float4* a0 = reinterpret_cast<const float4*>(xout5);
    const float4* a1 = reinterpret_cast<const float4*>(xout5 + (size_t)NELEM);
    const float4* a2 = reinterpret_cast<const float4*>(xout5 + (size_t)2 * NELEM);
    const float4* a3 = reinterpret_cast<const float4*>(xout5 + (size_t)3 * NELEM);
    const float4* gh = reinterpret_cast<const float4*>(xout5 + (size_t)4 * NELEM);
    size_t stride = (size_t)gridDim.x * blockDim.x;
    for (size_t i = (size_t)blockIdx.x * blockDim.x + threadIdx.x; i < NELEM / 4; i += stride) {
        float4 s0 = a0[i], s1 = a1[i], s2 = a2[i], s3 = a3[i], g = gh[i];
        float4 o;
        o.x = (s0.x + s1.x + s2.x + s3.x + rate * g.x) * inv6;
        o.y = (s0.y + s1.y + s2.y + s3.y + rate * g.y) * inv6;
        o.z = (s0.z + s1.z + s2.z + s3.z + rate * g.z) * inv6;
        o.w = (s0.w + s1.w + s2.w + s3.w + rate * g.w) * inv6;
        reinterpret_cast<float4*>(out)[i] = o;
    }
}

// ---------------- orchestration ----------------
extern "C" void kernel_launch(void* const* d_in, const int* in_sizes, int n_in,
                              void* d_out, int out_size)
{
    const float* x = (const float*)d_in[0];
    const float* p[12];
    const float* g[12];
    for (int i = 0; i < 12; i++) p[i] = (const float*)d_in[2 + i];
    for (int i = 0; i < 12; i++) g[i] = (const float*)d_in[14 + i];

    __nv_bfloat16 *xn, *qkv, *attno, *ffh, *wqkvt, *wot, *w1t, *w2t;
    float *x2, *xout, *meaneo, *stats;
    cudaGetSymbolAddress((void**)&xn, d_xn);
    cudaGetSymbolAddress((void**)&qkv, d_qkv);
    cudaGetSymbolAddress((void**)&attno, d_attno);
    cudaGetSymbolAddress((void**)&x2, d_x2);
    cudaGetSymbolAddress((void**)&ffh, d_ffh);
    cudaGetSymbolAddress((void**)&xout, d_xout);
    cudaGetSymbolAddress((void**)&meaneo, d_meaneo);
    cudaGetSymbolAddress((void**)&stats, d_stats);
    cudaGetSymbolAddress((void**)&wqkvt, d_wqkvt);
    cudaGetSymbolAddress((void**)&wot, d_wot);
    cudaGetSymbolAddress((void**)&w1t, d_w1t);
    cudaGetSymbolAddress((void**)&w2t, d_w2t);

    const int GEMM_SMEM = STGH * 3 * 2;
    cudaFuncSetAttribute(gemm5bf<0, __nv_bfloat16>, cudaFuncAttributeMaxDynamicSharedMemorySize, GEMM_SMEM);
    cudaFuncSetAttribute(gemm5bf<1, __nv_bfloat16>, cudaFuncAttributeMaxDynamicSharedMemorySize, GEMM_SMEM);
    cudaFuncSetAttribute(gemm5bf<2, float>,         cudaFuncAttributeMaxDynamicSharedMemorySize, GEMM_SMEM);
    cudaFuncSetAttribute(flash_kernel,              cudaFuncAttributeMaxDynamicSharedMemorySize, FLASH_SMEM);

    cudaMemsetAsync(meaneo, 0, 4 * DD * sizeof(float));
    cudaMemsetAsync(stats, 0, 4 * sizeof(float));

    // fused weight transpose+bf16
    wtrans4_kernel<<<dim3(3072, NE), dim3(32, 8)>>>(
        p[2], g[2], wqkvt, p[4], g[4], wot, p[8], g[8], w1t, p[10], g[10], w2t);

    // LN1 (x shared)
    ln5_kernel<<<dim3(BL, NE), 128>>>(x, 0, 1, p[0], g[0], p[1], g[1], xn);
    // QKV
    gemm5bf<0, __nv_bfloat16><<<dim3(12, 32, NE), 256, GEMM_SMEM>>>(
        xn, (size_t)NELEM, wqkvt, (size_t)3 * DD * DD,
        p[3], g[3], 3 * DD, nullptr, 0, 0, qkv, (size_t)BL * 3 * DD, 3 * DD, DD);
    // flash attention
    flash_kernel<<<dim3(4, 64, NE), 256, FLASH_SMEM>>>(qkv, attno);
    // O projection + residual(x)
    gemm5bf<2, float><<<dim3(4, 32, NE), 256, GEMM_SMEM>>>(
        attno, (size_t)NELEM, wot, (size_t)DD * DD,
        p[5], g[5], DD, x, 0, 1, x2, (size_t)NELEM, DD, DD);
    // LN2
    ln5_kernel<<<dim3(BL, NE), 128>>>(x2, (size_t)NELEM, 0, p[6], g[6], p[7], g[7], xn);
    // FFN1 + gelu
    gemm5bf<1, __nv_bfloat16><<<dim3(16, 32, NE), 256, GEMM_SMEM>>>(
        xn, (size_t)NELEM, w1t, (size_t)4 * DD * DD,
        p[9], g[9], 4 * DD, nullptr, 0, 0, ffh, (size_t)BL * 4 * DD, 4 * DD, DD);
    // FFN2 + residual(x2)
    gemm5bf<2, float><<<dim3(4, 32, NE), 256, GEMM_SMEM>>>(
        ffh, (size_t)BL * 4 * DD, w2t, (size_t)4 * DD * DD,
        p[11], g[11], DD, x2, (size_t)NELEM, 0, xout, (size_t)NELEM, DD, 4 * DD);

    // fused stats + finalize + combine
    stats_kernel<<<32, 512>>>(x, xout, meaneo, stats);
    finalize_kernel<<<1, 256>>>(meaneo, stats);
    combine_kernel<<<1024, 256>>>(xout, stats, (float*)d_out);
}

// round 15
// speedup vs baseline: 1.0088x; 1.0055x over previous
#include <cuda_runtime.h>
#include <cuda_bf16.h>
#include <math.h>
#include <stdint.h>

#define BB 8
#define LL 512
#define DD 512
#define HH 8
#define DH 64
#define BL 4096
#define NELEM 2097152
#define NE 5                    // 4 primary + ghost0

// ---------------- scratch (static device globals) ----------------
__device__ __nv_bfloat16 d_xn[(size_t)NE * BL * DD];
__device__ __nv_bfloat16 d_qkv[(size_t)NE * BL * 3 * DD];
__device__ __nv_bfloat16 d_attno[(size_t)NE * BL * DD];
__device__ float         d_x2[(size_t)NE * BL * DD];
__device__ __nv_bfloat16 d_ffh[(size_t)NE * BL * 4 * DD];
__device__ float         d_xout[(size_t)NE * BL * DD];
__device__ __nv_bfloat16 d_wqkvt[(size_t)NE * 3 * DD * DD];  // [N=1536][K=512]
__device__ __nv_bfloat16 d_wot[(size_t)NE * DD * DD];
__device__ __nv_bfloat16 d_w1t[(size_t)NE * 4 * DD * DD];    // [2048][512]
__device__ __nv_bfloat16 d_w2t[(size_t)NE * 4 * DD * DD];    // [512][2048]
__device__ float d_meaneo[4 * DD];
__device__ float d_stats[4];

// ---------------- helpers ----------------
__device__ __forceinline__ float warp_sum(float v) {
#pragma unroll
    for (int o = 16; o > 0; o >>= 1) v += __shfl_xor_sync(0xffffffffu, v, o);
    return v;
}
__device__ __forceinline__ float gelu_tanh(float v) {
    float c = 0.7978845608028654f * (v + 0.044715f * v * v * v);
    return 0.5f * v * (1.0f + tanhf(c));
}
__device__ __forceinline__ uint32_t packbf(float lo, float hi) {
    __nv_bfloat162 v = __floats2bfloat162_rn(lo, hi);
    return *reinterpret_cast<uint32_t*>(&v);
}
__device__ __forceinline__ void mma16(float* c, const uint32_t* a, const uint32_t* b) {
    asm volatile(
        "mma.sync.aligned.m16n8k16.row.col.f32.bf16.bf16.f32 "
        "{%0,%1,%2,%3},{%4,%5,%6,%7},{%8,%9},{%0,%1,%2,%3};\n"
        : "+f"(c[0]), "+f"(c[1]), "+f"(c[2]), "+f"(c[3])
        : "r"(a[0]), "r"(a[1]), "r"(a[2]), "r"(a[3]), "r"(b[0]), "r"(b[1]));
}
__device__ __forceinline__ void ldsm_x4(uint32_t& r0, uint32_t& r1, uint32_t& r2, uint32_t& r3,
                                        const void* p) {
    uint32_t a = (uint32_t)__cvta_generic_to_shared(p);
    asm volatile("ldmatrix.sync.aligned.m8n8.x4.shared.b16 {%0,%1,%2,%3}, [%4];\n"
                 : "=r"(r0), "=r"(r1), "=r"(r2), "=r"(r3) : "r"(a));
}
__device__ __forceinline__ void ldsm_x2_trans(uint32_t& r0, uint32_t& r1, const void* p) {
    uint32_t a = (uint32_t)__cvta_generic_to_shared(p);
    asm volatile("ldmatrix.sync.aligned.m8n8.x2.trans.shared.b16 {%0,%1}, [%2];\n"
                 : "=r"(r0), "=r"(r1) : "r"(a));
}
__device__ __forceinline__ void cpa16(void* dst, const void* src) {
    uint32_t d = (uint32_t)__cvta_generic_to_shared(dst);
    asm volatile("cp.async.cg.shared.global [%0], [%1], 16;\n" :: "r"(d), "l"(src));
}
#define CP_COMMIT() asm volatile("cp.async.commit_group;\n" ::: "memory")
#define CP_WAIT1()  asm volatile("cp.async.wait_group 1;\n" ::: "memory")
#define CP_WAIT0()  asm volatile("cp.async.wait_group 0;\n" ::: "memory")

// ---------------- fused weight transpose+bf16 for all 4 weight types, 5 experts --------------
__global__ void wtrans4_kernel(const float* p0, const float* g0, __nv_bfloat16* o0,
                               const float* p1, const float* g1, __nv_bfloat16* o1,
                               const float* p2, const float* g2, __nv_bfloat16* o2,
                               const float* p3, const float* g3, __nv_bfloat16* o3)
{
    __shared__ float s[32][33];
    int e = blockIdx.y;
    int idx = blockIdx.x;
    const float *p, *g; __nv_bfloat16* o; int K, N;
    if (idx < 768)       { p = p0; g = g0; o = o0; K = 512;  N = 1536; }
    else if (idx < 1024) { p = p1; g = g1; o = o1; K = 512;  N = 512;  idx -= 768; }
    else if (idx < 2048) { p = p2; g = g2; o = o2; K = 512;  N = 2048; idx -= 1024; }
    else                 { p = p3; g = g3; o = o3; K = 2048; N = 512;  idx -= 2048; }
    int tkx = K >> 5;
    int k0 = (idx % tkx) * 32, n0 = (idx / tkx) * 32;
    const float* in = (e < 4) ? p + (size_t)e * K * N : g;
    __nv_bfloat16* out = o + (size_t)e * K * N;
    int tx = threadIdx.x, ty = threadIdx.y;   // 32 x 8
#pragma unroll
    for (int r = 0; r < 4; r++)
        s[ty + 8 * r][tx] = in[(size_t)(k0 + ty + 8 * r) * N + n0 + tx];
    __syncthreads();
#pragma unroll
    for (int r = 0; r < 4; r++)
        out[(size_t)(n0 + ty + 8 * r) * K + k0 + tx] = __float2bfloat16_rn(s[tx][ty + 8 * r]);
}

// ---------------- LayerNorm over 5 experts; fp32 in, bf16 out ----------------
__global__ void ln5_kernel(const float* __restrict__ X, size_t sX, int xShared,
                           const float* __restrict__ sP, const float* __restrict__ sG,
                           const float* __restrict__ bP, const float* __restrict__ bG,
                           __nv_bfloat16* __restrict__ Y)
{
    __shared__ float sm[8];
    int e = blockIdx.y;
    const float* x = (xShared ? X : X + (size_t)e * sX) + (size_t)blockIdx.x * DD;
    const float* sc = (e < 4 ? sP + (size_t)e * DD : sG);
    const float* bi = (e < 4 ? bP + (size_t)e * DD : bG);
    __nv_bfloat16* y = Y + (size_t)e * NELEM + (size_t)blockIdx.x * DD;
    int t = threadIdx.x;
    float4 v = reinterpret_cast<const float4*>(x)[t];
    float s = v.x + v.y + v.z + v.w;
    float q = v.x * v.x + v.y * v.y + v.z * v.z + v.w * v.w;
    s = warp_sum(s); q = warp_sum(q);
    if ((t & 31) == 0) { sm[t >> 5] = s; sm[4 + (t >> 5)] = q; }
    __syncthreads();
    float S = sm[0] + sm[1] + sm[2] + sm[3];
    float Q = sm[4] + sm[5] + sm[6] + sm[7];
    float mean = S * (1.0f / DD);
    float var  = Q * (1.0f / DD) - mean * mean;
    float inv  = rsqrtf(var + 1e-5f);
    float4 scv = reinterpret_cast<const float4*>(sc)[t];
    float4 biv = reinterpret_cast<const float4*>(bi)[t];
    uint2 u;
    u.x = packbf((v.x - mean) * inv * scv.x + biv.x, (v.y - mean) * inv * scv.y + biv.y);
    u.y = packbf((v.z - mean) * inv * scv.z + biv.z, (v.w - mean) * inv * scv.w + biv.w);
    *reinterpret_cast<uint2*>(y + 4 * t) = u;
}

// ---------------- bf16 GEMM: 128x128 tiles, BK=32, ldmatrix fragments (R6 proven) ------------
#define AH 40
#define STGH (2 * 128 * AH)

template<int EPI, typename OT>
__global__ void __launch_bounds__(256)
gemm5bf(const __nv_bfloat16* __restrict__ Ab, size_t sA,
        const __nv_bfloat16* __restrict__ Wb, size_t sW,
        const float* __restrict__ bP, const float* __restrict__ bG, int sB,
        const float* __restrict__ Rb, size_t sR, int rShared,
        OT* __restrict__ Cb, size_t sC, int N, int K)
{
    extern __shared__ __nv_bfloat16 smh[];
    int e = blockIdx.z;
    const __nv_bfloat16* A = Ab + (size_t)e * sA;
    const __nv_bfloat16* W = Wb + (size_t)e * sW;
    const float* bias = (e < 4 ? bP + (size_t)e * sB : bG);
    const float* R = Rb ? (rShared ? Rb : Rb + (size_t)e * sR) : nullptr;
    OT* C = Cb + (size_t)e * sC;

    int tid = threadIdx.x;
    int lane = tid & 31, warp = tid >> 5;
    int g = lane >> 2, tig = lane & 3;
    int lr = lane & 7, sel = lane >> 3;
    int wm = (warp >> 1) * 32, wn = (warp & 1) * 64;
    int bm = blockIdx.y * 128, bn = blockIdx.x * 128;

    float c[2][8][4];
#pragma unroll
    for (int i = 0; i < 2; i++)
#pragma unroll
        for (int j = 0; j < 8; j++)
#pragma unroll
            for (int q = 0; q < 4; q++) c[i][j][q] = 0.f;

    int KT = K >> 5;

#pragma unroll
    for (int s = 0; s < 2; s++) {
        __nv_bfloat16* As = smh + s * STGH;
        __nv_bfloat16* Bs = As + 128 * AH;
        int k0 = s * 32;
#pragma unroll
        for (int i = 0; i < 2; i++) {
            int idx = tid + i * 256;
            int row = idx >> 2, c8 = idx & 3;
            cpa16(As + row * AH + c8 * 8, A + (size_t)(bm + row) * K + k0 + c8 * 8);
            cpa16(Bs + row * AH + c8 * 8, W + (size_t)(bn + row) * K + k0 + c8 * 8);
        }
        CP_COMMIT();
    }

    for (int it = 0; it < KT; it++) {
        CP_WAIT1();
        __syncthreads();
        const __nv_bfloat16* As = smh + (it % 3) * STGH;
        const __nv_bfloat16* Bs = As + 128 * AH;
#pragma unroll
        for (int ks = 0; ks < 2; ks++) {
            int kb = ks * 16;
            uint32_t af[2][4], bf[8][2];
#pragma unroll
            for (int mt = 0; mt < 2; mt++) {
                const __nv_bfloat16* pa =
                    As + (size_t)(wm + mt * 16 + lr + (sel & 1) * 8) * AH + kb + (sel >> 1) * 8;
                ldsm_x4(af[mt][0], af[mt][1], af[mt][2], af[mt][3], pa);
            }
#pragma unroll
            for (int nt2 = 0; nt2 < 4; nt2++) {
                const __nv_bfloat16* pb =
                    Bs + (size_t)(wn + nt2 * 16 + lr + (sel >> 1) * 8) * AH + kb + (sel & 1) * 8;
                ldsm_x4(bf[2 * nt2][0], bf[2 * nt2][1], bf[2 * nt2 + 1][0], bf[2 * nt2 + 1][1], pb);
            }
#pragma unroll
            for (int mt = 0; mt < 2; mt++)
#pragma unroll
                for (int nt = 0; nt < 8; nt++)
                    mma16(c[mt][nt], af[mt], bf[nt]);
        }
        int nx = it + 2;
        if (nx < KT) {
            __nv_bfloat16* Asw = smh + (nx % 3) * STGH;
            __nv_bfloat16* Bsw = Asw + 128 * AH;
            int k0 = nx * 32;
#pragma unroll
            for (int i = 0; i < 2; i++) {
                int idx = tid + i * 256;
                int row = idx >> 2, c8 = idx & 3;
                cpa16(Asw + row * AH + c8 * 8, A + (size_t)(bm + row) * K + k0 + c8 * 8);
                cpa16(Bsw + row * AH + c8 * 8, W + (size_t)(bn + row) * K + k0 + c8 * 8);
            }
        }
        CP_COMMIT();
    }

#pragma unroll
    for (int mt = 0; mt < 2; mt++) {
        int r0 = bm + wm + mt * 16 + g;
        int r1 = r0 + 8;
#pragma unroll
        for (int nt = 0; nt < 8; nt++) {
            int cc = bn + wn + nt * 8 + tig * 2;
            float b0 = bias[cc], b1 = bias[cc + 1];
            float v00 = c[mt][nt][0] + b0, v01 = c[mt][nt][1] + b1;
            float v10 = c[mt][nt][2] + b0, v11 = c[mt][nt][3] + b1;
            if (EPI == 1) {
                v00 = gelu_tanh(v00); v01 = gelu_tanh(v01);
                v10 = gelu_tanh(v10); v11 = gelu_tanh(v11);
            }
            if (EPI == 2) {
                v00 += R[(size_t)r0 * N + cc]; v01 += R[(size_t)r0 * N + cc + 1];
                v10 += R[(size_t)r1 * N + cc]; v11 += R[(size_t)r1 * N + cc + 1];
            }
            if (sizeof(OT) == 2) {
                *reinterpret_cast<uint32_t*>((char*)(C + (size_t)r0 * N + cc)) = packbf(v00, v01);
                *reinterpret_cast<uint32_t*>((char*)(C + (size_t)r1 * N + cc)) = packbf(v10, v11);
            } else {
                *reinterpret_cast<float2*>((char*)(C + (size_t)r0 * N + cc)) = make_float2(v00, v01);
                *reinterpret_cast<float2*>((char*)(C + (size_t)r1 * N + cc)) = make_float2(v10, v11);
            }
        }
    }
}

// ---------------- flash attention bf16: cp.async double-buffered K/V ----------------
// smem halves: Qs[128*72], then K/V buffers: {K0,V0,K1,V1} each 64*72
#define FQ 0
#define FKV (128 * 72)
#define KVSZ (64 * 72)
#define FLASH_SMEM ((FKV + 4 * KVSZ) * 2)

__global__ void __launch_bounds__(256)
flash_kernel(const __nv_bfloat16* __restrict__ qkv5, __nv_bfloat16* __restrict__ attno5)
{
    extern __shared__ __nv_bfloat16 smh[];
    __nv_bfloat16* Qs = smh + FQ;

    int e = blockIdx.z;
    const __nv_bfloat16* qkv = qkv5 + (size_t)e * BL * 3 * DD;
    __nv_bfloat16* attno = attno5 + (size_t)e * NELEM;
    int bh = blockIdx.y;
    int b = bh >> 3, h = bh & 7;
    int i0 = blockIdx.x * 128;
    int tid = threadIdx.x;
    int lane = tid & 31, warp = tid >> 5;
    int g = lane >> 2, tig = lane & 3;
    int lr = lane & 7, sel = lane >> 3;
    int wm = warp * 16;

    // prologue: stage Q + K/V tile 0 (one cp.async group)
#pragma unroll
    for (int i = 0; i < 4; i++) {
        int idx = tid + i * 256;
        int m = idx >> 3, c8 = idx & 7;
        cpa16(Qs + m * 72 + c8 * 8,
              qkv + (size_t)(b * LL + i0 + m) * (3 * DD) + h * DH + c8 * 8);
    }
    {
        __nv_bfloat16* Ks = smh + FKV;
        __nv_bfloat16* Vs = Ks + KVSZ;
#pragma unroll
        for (int i = 0; i < 2; i++) {
            int idx = tid + i * 256;
            int r = idx >> 3, c8 = idx & 7;
            cpa16(Ks + r * 72 + c8 * 8,
                  qkv + (size_t)(b * LL + r) * (3 * DD) + DD + h * DH + c8 * 8);
            cpa16(Vs + r * 72 + c8 * 8,
                  qkv + (size_t)(b * LL + r) * (3 * DD) + 2 * DD + h * DH + c8 * 8);
        }
        CP_COMMIT();
    }

    float o[8][4];
#pragma unroll
    for (int j = 0; j < 8; j++)
#pragma unroll
        for (int q = 0; q < 4; q++) o[j][q] = 0.f;
    float mrow[2] = { -1e30f, -1e30f };
    float lrow[2] = { 0.f, 0.f };

    for (int jt = 0; jt < 8; jt++) {
        __syncthreads();    // all warps done with buffer (jt+1)&1 from iteration jt-1
        if (jt + 1 < 8) {   // prefetch tile jt+1
            __nv_bfloat16* Ks = smh + FKV + ((jt + 1) & 1) * 2 * KVSZ;
            __nv_bfloat16* Vs = Ks + KVSZ;
            int j0 = (jt + 1) * 64;
#pragma unroll
            for (int i = 0; i < 2; i++) {
                int idx = tid + i * 256;
                int r = idx >> 3, c8 = idx & 7;
                cpa16(Ks + r * 72 + c8 * 8,
                      qkv + (size_t)(b * LL + j0 + r) * (3 * DD) + DD + h * DH + c8 * 8);
                cpa16(Vs + r * 72 + c8 * 8,
                      qkv + (size_t)(b * LL + j0 + r) * (3 * DD) + 2 * DD + h * DH + c8 * 8);
            }
            CP_COMMIT();
            CP_WAIT1();     // tile jt (and Q on jt=0) has landed
        } else {
            CP_WAIT0();
        }
        __syncthreads();

        const __nv_bfloat16* Ks = smh + FKV + (jt & 1) * 2 * KVSZ;
        const __nv_bfloat16* Vs = Ks + KVSZ;

        // S = Q @ K^T (16x64 per warp)
        float c[8][4];
#pragma unroll
        for (int j = 0; j < 8; j++)
#pragma unroll
            for (int q = 0; q < 4; q++) c[j][q] = 0.f;
#pragma unroll
        for (int ks = 0; ks < 4; ks++) {
            int kb = ks * 16;
            uint32_t af[4], bf[8][2];
            const __nv_bfloat16* pa =
                Qs + (size_t)(wm + lr + (sel & 1) * 8) * 72 + kb + (sel >> 1) * 8;
            ldsm_x4(af[0], af[1], af[2], af[3], pa);
#pragma unroll
            for (int nt2 = 0; nt2 < 4; nt2++) {
                const __nv_bfloat16* pb =
                    Ks + (size_t)(nt2 * 16 + lr + (sel >> 1) * 8) * 72 + kb + (sel & 1) * 8;
                ldsm_x4(bf[2 * nt2][0], bf[2 * nt2][1], bf[2 * nt2 + 1][0], bf[2 * nt2 + 1][1], pb);
            }
#pragma unroll
            for (int nt = 0; nt < 8; nt++) mma16(c[nt], af, bf[nt]);
        }
#pragma unroll
        for (int nt = 0; nt < 8; nt++)
#pragma unroll
            for (int q = 0; q < 4; q++) c[nt][q] *= 0.125f;

        // online softmax
        float mx0 = -1e30f, mx1 = -1e30f;
#pragma unroll
        for (int nt = 0; nt < 8; nt++) {
            mx0 = fmaxf(mx0, fmaxf(c[nt][0], c[nt][1]));
            mx1 = fmaxf(mx1, fmaxf(c[nt][2], c[nt][3]));
        }
        mx0 = fmaxf(mx0, __shfl_xor_sync(0xffffffffu, mx0, 1));
        mx0 = fmaxf(mx0, __shfl_xor_sync(0xffffffffu, mx0, 2));
        mx1 = fmaxf(mx1, __shfl_xor_sync(0xffffffffu, mx1, 1));
        mx1 = fmaxf(mx1, __shfl_xor_sync(0xffffffffu, mx1, 2));
        float mn0 = fmaxf(mrow[0], mx0), mn1 = fmaxf(mrow[1], mx1);
        float sc0 = __expf(mrow[0] - mn0), sc1 = __expf(mrow[1] - mn1);
        mrow[0] = mn0; mrow[1] = mn1;
        float rs0 = 0.f, rs1 = 0.f;
#pragma unroll
        for (int nt = 0; nt < 8; nt++) {
            c[nt][0] = __expf(c[nt][0] - mn0); c[nt][1] = __expf(c[nt][1] - mn0);
            c[nt][2] = __expf(c[nt][2] - mn1); c[nt][3] = __expf(c[nt][3] - mn1);
            rs0 += c[nt][0] + c[nt][1];
            rs1 += c[nt][2] + c[nt][3];
            o[nt][0] *= sc0; o[nt][1] *= sc0; o[nt][2] *= sc1; o[nt][3] *= sc1;
        }
        rs0 += __shfl_xor_sync(0xffffffffu, rs0, 1);
        rs0 += __shfl_xor_sync(0xffffffffu, rs0, 2);
        rs1 += __shfl_xor_sync(0xffffffffu, rs1, 1);
        rs1 += __shfl_xor_sync(0xffffffffu, rs1, 2);
        lrow[0] = lrow[0] * sc0 + rs0;
        lrow[1] = lrow[1] * sc1 + rs1;

        // O += P @ V ; P register-direct, V via ldmatrix.trans
        const __nv_bfloat16* vrow = Vs + (size_t)(lane & 15) * 72;
#pragma unroll
        for (int ks = 0; ks < 4; ks++) {
            uint32_t af[4];
            af[0] = packbf(c[2 * ks][0],     c[2 * ks][1]);
            af[1] = packbf(c[2 * ks][2],     c[2 * ks][3]);
            af[2] = packbf(c[2 * ks + 1][0], c[2 * ks + 1][1]);
            af[3] = packbf(c[2 * ks + 1][2], c[2 * ks + 1][3]);
            const __nv_bfloat16* vb = vrow + ks * 16 * 72;
#pragma unroll
            for (int nt = 0; nt < 8; nt++) {
                uint32_t b0, b1;
                ldsm_x2_trans(b0, b1, vb + nt * 8);
                uint32_t bfr[2] = { b0, b1 };
                mma16(o[nt], af, bfr);
            }
        }
    }

    float inv0 = __frcp_rn(lrow[0]), inv1 = __frcp_rn(lrow[1]);
    int r0 = i0 + wm + g, r1 = r0 + 8;
#pragma unroll
    for (int nt = 0; nt < 8; nt++) {
        int cc = h * DH + nt * 8 + tig * 2;
        *reinterpret_cast<uint32_t*>(attno + (size_t)(b * LL + r0) * DD + cc) =
            packbf(o[nt][0] * inv0, o[nt][1] * inv0);
        *reinterpret_cast<uint32_t*>(attno + (size_t)(b * LL + r1) * DD + cc) =
            packbf(o[nt][2] * inv1, o[nt][3] * inv1);
    }
}

// ---------------- fused stats: per-expert column sums + uvar partials (one pass) -------------
__global__ void stats_kernel(const float* __restrict__ x, const float* __restrict__ xout5,
                             float* __restrict__ meaneo, float* __restrict__ stats)
{
    __shared__ float sm[32];
    const float* a0 = xout5;
    const float* a1 = xout5 + (size_t)NELEM;
    const float* a2 = xout5 + (size_t)2 * NELEM;
    const float* a3 = xout5 + (size_t)3 * NELEM;
    int t = threadIdx.x;                 // 512 (one per column)
    int r0 = blockIdx.x * 128;
    float m0 = 0.f, m1 = 0.f, m2 = 0.f, m3 = 0.f, s1 = 0.f, s2 = 0.f;
    for (int r = r0; r < r0 + 128; r++) {
        size_t idx = (size_t)r * DD + t;
        float v0 = a0[idx], v1 = a1[idx], v2 = a2[idx], v3 = a3[idx];
        m0 += v0; m1 += v1; m2 += v2; m3 += v3;
        float d = x[idx] - 0.25f * (v0 + v1 + v2 + v3);
        s1 += d; s2 += d * d;
    }
    atomicAdd(&meaneo[t], m0);
    atomicAdd(&meaneo[DD + t], m1);
    atomicAdd(&meaneo[2 * DD + t], m2);
    atomicAdd(&meaneo[3 * DD + t], m3);
    s1 = warp_sum(s1); s2 = warp_sum(s2);
    int w = t >> 5;                      // 16 warps
    if ((t & 31) == 0) { sm[w] = s1; sm[16 + w] = s2; }
    __syncthreads();
    if (t == 0) {
        float a = 0.f, b = 0.f;
        for (int i = 0; i < 16; i++) { a += sm[i]; b += sm[16 + i]; }
        atomicAdd(&stats[0], a);
        atomicAdd(&stats[1], b);
    }
}

// ---------------- gram / ortho / uvar / rate ----------------
__global__ void finalize_kernel(const float* __restrict__ meaneo, float* __restrict__ stats)
{
    __shared__ float sd[16];
    int t = threadIdx.x;
    if (t < 16) sd[t] = 0.f;
    __syncthreads();
    float l[4][4] = {};
    for (int c = t; c < DD; c += 256) {
        float v[4];
#pragma unroll
        for (int i = 0; i < 4; i++) v[i] = meaneo[i * DD + c];
#pragma unroll
        for (int i = 0; i < 4; i++)
#pragma unroll
            for (int j = i; j < 4; j++) l[i][j] += v[i] * v[j];
    }
#pragma unroll
    for (int i = 0; i < 4; i++)
#pragma unroll
        for (int j = i; j < 4; j++) atomicAdd(&sd[i * 4 + j], l[i][j]);
    __syncthreads();
    if (t == 0) {
        float nrm[4];
        for (int i = 0; i < 4; i++) nrm[i] = sqrtf(sd[i * 4 + i]);
        float off = 0.f;
        for (int i = 0; i < 4; i++)
            for (int j = 0; j < 4; j++) {
                float dot = (i <= j) ? sd[i * 4 + j] : sd[j * 4 + i];
                float gg = dot / (nrm[i] * nrm[j]);
                float dlt = gg - (i == j ? 1.0f : 0.0f);
                off += dlt * dlt;
            }
        float ortho = 1.0f - off / 16.0f;
        float S1 = stats[0], S2 = stats[1];
        const float N = (float)NELEM;
        float uvar = (S2 - S1 * S1 / N) / (N - 1.0f);
        float sat = ortho * uvar;
        stats[2] = (sat > 0.01f) ? 0.01f : 0.0f;
    }
}

// ---------------- combine: (sum_prim + rate * ghost0) / 6 ----------------
__global__ void combine_kernel(const float* __restrict__ xout5,
                               const float* __restrict__ stats, float* __restrict__ out)
{
    float rate = stats[2];
    const float inv6 = 1.0f / 6.0f;
    const float4* a0 = reinterpret_cast<const float4*>(xout5);
    const float4* a1 = reinterpret_cast<const float4*>(xout5 + (size_t)NELEM);
    const float4* a2 = reinterpret_cast<const float4*>(xout5 + (size_t)2 * NELEM);
    const float4* a3 = reinterpret_cast<const float4*>(xout5 + (size_t)3 * NELEM);
    const float4* gh = reinterpret_cast<const float4*>(xout5 + (size_t)4 * NELEM);
    size_t stride = (size_t)gridDim.x * blockDim.x;
    for (size_t i = (size_t)blockIdx.x * blockDim.x + threadIdx.x; i < NELEM / 4; i += stride) {
        float4 s0 = a0[i], s1 = a1[i], s2 = a2[i], s3 = a3[i], g = gh[i];
        float4 o;
        o.x = (s0.x + s1.x + s2.x + s3.x + rate * g.x) * inv6;
        o.y = (s0.y + s1.y + s2.y + s3.y + rate * g.y) * inv6;
        o.z = (s0.z + s1.z + s2.z + s3.z + rate * g.z) * inv6;
        o.w = (s0.w + s1.w + s2.w + s3.w + rate * g.w) * inv6;
        reinterpret_cast<float4*>(out)[i] = o;
    }
}

// ---------------- orchestration ----------------
extern "C" void kernel_launch(void* const* d_in, const int* in_sizes, int n_in,
                              void* d_out, int out_size)
{
    const float* x = (const float*)d_in[0];
    const float* p[12];
    const float* g[12];
    for (int i = 0; i < 12; i++) p[i] = (const float*)d_in[2 + i];
    for (int i = 0; i < 12; i++) g[i] = (const float*)d_in[14 + i];

    __nv_bfloat16 *xn, *qkv, *attno, *ffh, *wqkvt, *wot, *w1t, *w2t;
    float *x2, *xout, *meaneo, *stats;
    cudaGetSymbolAddress((void**)&xn, d_xn);
    cudaGetSymbolAddress((void**)&qkv, d_qkv);
    cudaGetSymbolAddress((void**)&attno, d_attno);
    cudaGetSymbolAddress((void**)&x2, d_x2);
    cudaGetSymbolAddress((void**)&ffh, d_ffh);
    cudaGetSymbolAddress((void**)&xout, d_xout);
    cudaGetSymbolAddress((void**)&meaneo, d_meaneo);
    cudaGetSymbolAddress((void**)&stats, d_stats);
    cudaGetSymbolAddress((void**)&wqkvt, d_wqkvt);
    cudaGetSymbolAddress((void**)&wot, d_wot);
    cudaGetSymbolAddress((void**)&w1t, d_w1t);
    cudaGetSymbolAddress((void**)&w2t, d_w2t);

    const int GEMM_SMEM = STGH * 3 * 2;
    cudaFuncSetAttribute(gemm5bf<0, __nv_bfloat16>, cudaFuncAttributeMaxDynamicSharedMemorySize, GEMM_SMEM);
    cudaFuncSetAttribute(gemm5bf<1, __nv_bfloat16>, cudaFuncAttributeMaxDynamicSharedMemorySize, GEMM_SMEM);
    cudaFuncSetAttribute(gemm5bf<2, float>,         cudaFuncAttributeMaxDynamicSharedMemorySize, GEMM_SMEM);
    cudaFuncSetAttribute(flash_kernel,              cudaFuncAttributeMaxDynamicSharedMemorySize, FLASH_SMEM);

    cudaMemsetAsync(meaneo, 0, 4 * DD * sizeof(float));
    cudaMemsetAsync(stats, 0, 4 * sizeof(float));

    // fused weight transpose+bf16
    wtrans4_kernel<<<dim3(3072, NE), dim3(32, 8)>>>(
        p[2], g[2], wqkvt, p[4], g[4], wot, p[8], g[8], w1t, p[10], g[10], w2t);

    // LN1 (x shared)
    ln5_kernel<<<dim3(BL, NE), 128>>>(x, 0, 1, p[0], g[0], p[1], g[1], xn);
    // QKV
    gemm5bf<0, __nv_bfloat16><<<dim3(12, 32, NE), 256, GEMM_SMEM>>>(
        xn, (size_t)NELEM, wqkvt, (size_t)3 * DD * DD,
        p[3], g[3], 3 * DD, nullptr, 0, 0, qkv, (size_t)BL * 3 * DD, 3 * DD, DD);
    // flash attention
    flash_kernel<<<dim3(4, 64, NE), 256, FLASH_SMEM>>>(qkv, attno);
    // O projection + residual(x)
    gemm5bf<2, float><<<dim3(4, 32, NE), 256, GEMM_SMEM>>>(
        attno, (size_t)NELEM, wot, (size_t)DD * DD,
        p[5], g[5], DD, x, 0, 1, x2, (size_t)NELEM, DD, DD);
    // LN2
    ln5_kernel<<<dim3(BL, NE), 128>>>(x2, (size_t)NELEM, 0, p[6], g[6], p[7], g[7], xn);
    // FFN1 + gelu
    gemm5bf<1, __nv_bfloat16><<<dim3(16, 32, NE), 256, GEMM_SMEM>>>(
        xn, (size_t)NELEM, w1t, (size_t)4 * DD * DD,
        p[9], g[9], 4 * DD, nullptr, 0, 0, ffh, (size_t)BL * 4 * DD, 4 * DD, DD);
    // FFN2 + residual(x2)
    gemm5bf<2, float><<<dim3(4, 32, NE), 256, GEMM_SMEM>>>(
        ffh, (size_t)BL * 4 * DD, w2t, (size_t)4 * DD * DD,
        p[11], g[11], DD, x2, (size_t)NELEM, 0, xout, (size_t)NELEM, DD, 4 * DD);

    // fused stats + finalize + combine
    stats_kernel<<<32, 512>>>(x, xout, meaneo, stats);
    finalize_kernel<<<1, 256>>>(meaneo, stats);
    combine_kernel<<<1024, 256>>>(xout, stats, (float*)d_out);
}